// round 12
// baseline (speedup 1.0000x reference)
#include <cuda_runtime.h>
#include <cuda_bf16.h>
#include <cstdint>
#include <math.h>

#define P 4096
#define NTH 256
#define BM 128
#define BN 256
#define BKF 32                   // K elems per chunk
#define NCH (P / BKF)            // 128
#define LDT 40                   // padded smem row (bf16 elems) = 80B
#define TILE_A_B (128 * LDT * 2) // 10240 B (A tile, 128 rows)
#define TILE_B_B (256 * LDT * 2) // 20480 B (B tile, 256 rows)

// ---------------------------------------------------------------- scratch
__device__ __nv_bfloat16 g_sHi[(size_t)P * P];
__device__ __nv_bfloat16 g_sLo[(size_t)P * P];
__device__ __nv_bfloat16 g_tHi[(size_t)P * P];
__device__ __nv_bfloat16 g_tLo[(size_t)P * P];
__device__ __nv_bfloat16 g_Wb16[(size_t)P * P];
__device__ __nv_bfloat16 g_tgtT16[(size_t)P * P];
__device__ __nv_bfloat16 g_Wm16[(size_t)P * P];
__device__ __nv_bfloat16 g_PT16[(size_t)P * P];
__device__ float  g_srcT[(size_t)P * P];
__device__ float  g_W[P];
__device__ float  g_scale[P];
__device__ double g_s;
__device__ double g_ss;

// ---------------------------------------------------------------- helpers
__device__ __forceinline__ uint32_t smem_to_u32(const void* p) {
    uint32_t a;
    asm("{ .reg .u64 t; cvta.to.shared.u64 t, %1; cvt.u32.u64 %0, t; }" : "=r"(a) : "l"(p));
    return a;
}
__device__ __forceinline__ void ldsm4(uint32_t* r, uint32_t addr) {
    asm volatile("ldmatrix.sync.aligned.m8n8.x4.shared.b16 {%0,%1,%2,%3}, [%4];"
                 : "=r"(r[0]), "=r"(r[1]), "=r"(r[2]), "=r"(r[3]) : "r"(addr));
}
__device__ __forceinline__ void mma16816(float* d, const uint32_t* a, uint32_t b0, uint32_t b1) {
    asm volatile(
        "mma.sync.aligned.m16n8k16.row.col.f32.bf16.bf16.f32 "
        "{%0,%1,%2,%3}, {%4,%5,%6,%7}, {%8,%9}, {%0,%1,%2,%3};"
        : "+f"(d[0]), "+f"(d[1]), "+f"(d[2]), "+f"(d[3])
        : "r"(a[0]), "r"(a[1]), "r"(a[2]), "r"(a[3]), "r"(b0), "r"(b1));
}
#define CP_ASYNC16(dst, src) \
    asm volatile("cp.async.cg.shared.global [%0], [%1], 16;" :: "r"(dst), "l"(src) : "memory")
#define CP_COMMIT() asm volatile("cp.async.commit_group;" ::: "memory")

__device__ __forceinline__ void split2(float x, float y, uint32_t& h, uint32_t& l) {
    __nv_bfloat162 hb = __floats2bfloat162_rn(x, y);
    float2 hf = __bfloat1622float2(hb);
    __nv_bfloat162 lb = __floats2bfloat162_rn(x - hf.x, y - hf.y);
    h = *reinterpret_cast<uint32_t*>(&hb);
    l = *reinterpret_cast<uint32_t*>(&lb);
}
__device__ __forceinline__ uint32_t pack_bf16(float x, float y) {
    __nv_bfloat162 hb = __floats2bfloat162_rn(x, y);
    return *reinterpret_cast<uint32_t*>(&hb);
}

// ---------------------------------------------------------------- small kernels
__global__ void zero_kernel() { g_s = 0.0; g_ss = 0.0; }

__global__ void sumsq_kernel(const float* __restrict__ X) {
    __shared__ float sdata[NTH];
    float acc = 0.f;
    size_t n = (size_t)P * P;
    for (size_t i = (size_t)blockIdx.x * blockDim.x + threadIdx.x; i < n;
         i += (size_t)gridDim.x * blockDim.x) { float v = X[i]; acc += v * v; }
    sdata[threadIdx.x] = acc; __syncthreads();
    for (int s = NTH / 2; s > 0; s >>= 1) {
        if (threadIdx.x < s) sdata[threadIdx.x] += sdata[threadIdx.x + s];
        __syncthreads();
    }
    if (threadIdx.x == 0) atomicAdd(&g_s, (double)sdata[0]);
}

__global__ void rowsum_kernel(const float* __restrict__ Wb) {
    __shared__ float sdata[NTH];
    const float* rp = Wb + (size_t)blockIdx.x * P;
    float acc = 0.f;
    for (int j = threadIdx.x; j < P; j += NTH) acc += rp[j];
    sdata[threadIdx.x] = acc; __syncthreads();
    for (int s = NTH / 2; s > 0; s >>= 1) {
        if (threadIdx.x < s) sdata[threadIdx.x] += sdata[threadIdx.x + s];
        __syncthreads();
    }
    if (threadIdx.x == 0) g_W[blockIdx.x] = sdata[0];
}

__global__ void scale_kernel() {
    int i = blockIdx.x * blockDim.x + threadIdx.x;
    if (i < P) {
        float w = g_W[i], w2 = w * w;
        g_scale[i] = w2 / ((float)g_s * w2 + 1.0f);
    }
}

__global__ void convert_split_kernel(const float* __restrict__ in,
                                     __nv_bfloat16* __restrict__ hi,
                                     __nv_bfloat16* __restrict__ lo) {
    size_t n4 = (size_t)P * P / 4;
    for (size_t i = (size_t)blockIdx.x * blockDim.x + threadIdx.x; i < n4;
         i += (size_t)gridDim.x * blockDim.x) {
        float4 v = ((const float4*)in)[i];
        uint32_t h0, l0, h1, l1;
        split2(v.x, v.y, h0, l0);
        split2(v.z, v.w, h1, l1);
        ((uint2*)hi)[i] = make_uint2(h0, h1);
        ((uint2*)lo)[i] = make_uint2(l0, l1);
    }
}

__global__ void convert_plain_kernel(const float* __restrict__ in,
                                     __nv_bfloat16* __restrict__ o16) {
    size_t n4 = (size_t)P * P / 4;
    for (size_t i = (size_t)blockIdx.x * blockDim.x + threadIdx.x; i < n4;
         i += (size_t)gridDim.x * blockDim.x) {
        float4 v = ((const float4*)in)[i];
        ((uint2*)o16)[i] = make_uint2(pack_bf16(v.x, v.y), pack_bf16(v.z, v.w));
    }
}

__global__ void transpose_f32_kernel(const float* __restrict__ in, float* __restrict__ out) {
    __shared__ float tile[32][33];
    int x = blockIdx.x * 32 + threadIdx.x;
    int y0 = blockIdx.y * 32;
    for (int j = threadIdx.y; j < 32; j += 8)
        tile[j][threadIdx.x] = in[(size_t)(y0 + j) * P + x];
    __syncthreads();
    int x2 = blockIdx.y * 32 + threadIdx.x;
    int y2 = blockIdx.x * 32;
    for (int j = threadIdx.y; j < 32; j += 8)
        out[(size_t)(y2 + j) * P + x2] = tile[threadIdx.x][j];
}

__global__ void transpose_bf16_kernel(const float* __restrict__ in,
                                      __nv_bfloat16* __restrict__ out) {
    __shared__ float tile[32][33];
    int x = blockIdx.x * 32 + threadIdx.x;
    int y0 = blockIdx.y * 32;
    for (int j = threadIdx.y; j < 32; j += 8)
        tile[j][threadIdx.x] = in[(size_t)(y0 + j) * P + x];
    __syncthreads();
    int x2 = blockIdx.y * 32 + threadIdx.x;
    int y2 = blockIdx.x * 32;
    for (int j = threadIdx.y; j < 32; j += 8)
        out[(size_t)(y2 + j) * P + x2] = __float2bfloat16(tile[threadIdx.x][j]);
}

__global__ void final_kernel(float* __restrict__ out) { out[0] = (float)sqrt(g_ss); }

// ---------------------------------------------------------------- HMMA GEMM
// CTA tile 128x256, 8 warps of 64x64 (smem reads = 128B/MMA, crossbar-balanced).
// Inner window keeps only af[4][4] + 2-deep bf rotation to stay under 255 regs.
// SPLIT: hi/lo operands, 3 passes (hh, lh, hl).
template <int EPI, bool SPLIT, int NSTAGE>
__global__ void __launch_bounds__(NTH, 1)
gemm_hmma(const __nv_bfloat16* __restrict__ Ah_, const __nv_bfloat16* __restrict__ Al_,
          const __nv_bfloat16* __restrict__ Bh_, const __nv_bfloat16* __restrict__ Bl_,
          const float* __restrict__ Dg, float* __restrict__ Cf32,
          __nv_bfloat16* __restrict__ C16) {
    extern __shared__ char smem[];
    const uint32_t su = smem_to_u32(smem);
    const int tid = threadIdx.x;
    const int lane = tid & 31;
    const int wid = tid >> 5;
    const int rowBase = blockIdx.y * BM;
    const int colBase = blockIdx.x * BN;
    const int m64 = (wid & 1) * 64;
    const int n64 = (wid >> 1) * 64;
    const uint32_t bOff    = SPLIT ? 2 * TILE_A_B : TILE_A_B;
    const uint32_t STAGE_B = SPLIT ? 2 * (TILE_A_B + TILE_B_B) : (TILE_A_B + TILE_B_B);

    float acc[4][8][4];
#pragma unroll
    for (int i = 0; i < 4; i++)
#pragma unroll
        for (int j = 0; j < 8; j++)
#pragma unroll
            for (int q = 0; q < 4; q++) acc[i][j][q] = 0.f;

    auto issue = [&](int chunk) {
        const uint32_t sb = su + (uint32_t)(chunk % NSTAGE) * STAGE_B;
        const int k0 = chunk * BKF;
        const int nOp = SPLIT ? 2 : 1;
#pragma unroll
        for (int op = 0; op < nOp; op++) {
            const __nv_bfloat16* aSrc = op ? Al_ : Ah_;
            const uint32_t aBase = sb + (uint32_t)op * TILE_A_B;
#pragma unroll
            for (int t = 0; t < 2; t++) {
                int idx = tid + t * NTH;
                int row = idx >> 2, q = idx & 3;
                CP_ASYNC16(aBase + row * (LDT * 2) + q * 16,
                           aSrc + (size_t)(rowBase + row) * P + k0 + q * 8);
            }
            const __nv_bfloat16* bSrc = op ? Bl_ : Bh_;
            const uint32_t bBase = sb + bOff + (uint32_t)op * TILE_B_B;
#pragma unroll
            for (int t = 0; t < 4; t++) {
                int idx = tid + t * NTH;
                int row = idx >> 2, q = idx & 3;
                CP_ASYNC16(bBase + row * (LDT * 2) + q * 16,
                           bSrc + (size_t)(colBase + row) * P + k0 + q * 8);
            }
        }
    };

    // ldmatrix lane addressing (byte offsets, row stride 80B) — validated R6-R8
    const int aRowOff = (lane & 7) + ((lane >> 3) & 1) * 8;
    const int aCbOff  = (lane >> 4) * 16;
    const int bRowOff = (lane & 7) + ((lane >> 4) & 1) * 8;
    const int bCbOff  = ((lane >> 3) & 1) * 16;

#pragma unroll
    for (int s = 0; s < NSTAGE - 1; s++) { issue(s); CP_COMMIT(); }

#pragma unroll 1
    for (int c = 0; c < NCH; c++) {
        if (c + NSTAGE - 1 < NCH) issue(c + NSTAGE - 1);
        CP_COMMIT();
        asm volatile("cp.async.wait_group %0;" :: "n"(NSTAGE - 1) : "memory");
        __syncthreads();

        const uint32_t sb = su + (uint32_t)(c % NSTAGE) * STAGE_B;
        const uint32_t aH = sb, aL = sb + TILE_A_B;
        const uint32_t bH = sb + bOff, bL = bH + TILE_B_B;

        const int npass = SPLIT ? 3 : 1;
#pragma unroll
        for (int pass = 0; pass < npass; pass++) {
            uint32_t aBase = (pass == 1) ? aL : aH;  // hh, lh, hl
            uint32_t bBase = (pass == 2) ? bL : bH;
#pragma unroll
            for (int ks = 0; ks < 2; ks++) {
                uint32_t af[4][4];
#pragma unroll
                for (int mi = 0; mi < 4; mi++)
                    ldsm4(af[mi], aBase + (m64 + mi * 16 + aRowOff) * (LDT * 2) + ks * 32 + aCbOff);
                // 2-deep bf rotation: overlap next ldsm with current 8 MMAs
                uint32_t bf0[4], bf1[4];
                ldsm4(bf0, bBase + (n64 + 0 * 16 + bRowOff) * (LDT * 2) + ks * 32 + bCbOff);
#pragma unroll
                for (int np = 0; np < 4; np++) {
                    uint32_t* cur = (np & 1) ? bf1 : bf0;
                    uint32_t* nxt = (np & 1) ? bf0 : bf1;
                    if (np < 3)
                        ldsm4(nxt, bBase + (n64 + (np + 1) * 16 + bRowOff) * (LDT * 2) + ks * 32 + bCbOff);
#pragma unroll
                    for (int mi = 0; mi < 4; mi++) {
                        mma16816(acc[mi][np * 2 + 0], af[mi], cur[0], cur[1]);
                        mma16816(acc[mi][np * 2 + 1], af[mi], cur[2], cur[3]);
                    }
                }
            }
        }
        __syncthreads();
    }

    // ---------------- epilogue ----------------
    const int rq = lane >> 2;
    const int cq = (lane & 3) * 2;
    float locss = 0.f;
#pragma unroll
    for (int mi = 0; mi < 4; mi++) {
        int r0 = rowBase + m64 + mi * 16 + rq;
        int r1 = r0 + 8;
        float s0 = 0.f, s1 = 0.f;
        if (EPI == 0) { s0 = g_scale[r0]; s1 = g_scale[r1]; }
#pragma unroll
        for (int ni = 0; ni < 8; ni++) {
            int cg = colBase + n64 + ni * 8 + cq;
            float* d = acc[mi][ni];
            if (EPI == 0) {
                float v0 = s0 * d[0], v1 = s0 * d[1];
                float v2 = s1 * d[2], v3 = s1 * d[3];
                Cf32[(size_t)r0 * P + cg]     = v0;
                Cf32[(size_t)r0 * P + cg + 1] = v1;
                Cf32[(size_t)r1 * P + cg]     = v2;
                Cf32[(size_t)r1 * P + cg + 1] = v3;
                *(uint32_t*)(C16 + (size_t)r0 * P + cg) = pack_bf16(v0, v1);
                *(uint32_t*)(C16 + (size_t)r1 * P + cg) = pack_bf16(v2, v3);
            } else if (EPI == 1) {
                float2 x0 = *(const float2*)(Dg + (size_t)r0 * P + cg);
                float2 x1 = *(const float2*)(Dg + (size_t)r1 * P + cg);
                *(uint32_t*)(C16 + (size_t)r0 * P + cg) = pack_bf16(d[0] - x0.x, d[1] - x0.y);
                *(uint32_t*)(C16 + (size_t)r1 * P + cg) = pack_bf16(d[2] - x1.x, d[3] - x1.y);
            } else {
                locss += d[0] * d[0] + d[1] * d[1] + d[2] * d[2] + d[3] * d[3];
            }
        }
    }
    if (EPI == 2) {
        __syncthreads();
        float* red = (float*)smem;
        red[tid] = locss;
        __syncthreads();
        for (int s = NTH / 2; s > 0; s >>= 1) {
            if (tid < s) red[tid] += red[tid + s];
            __syncthreads();
        }
        if (tid == 0) atomicAdd(&g_ss, (double)red[0]);
    }
}

// ---------------------------------------------------------------- launch
extern "C" void kernel_launch(void* const* d_in, const int* in_sizes, int n_in,
                              void* d_out, int out_size) {
    const float* target = (const float*)d_in[0];
    const float* source = (const float*)d_in[1];
    const float* Wbeta  = (const float*)d_in[2];
    float* out = (float*)d_out;   // out[0]=loss, out[1:]=W_matrix

    __nv_bfloat16 *sHi, *sLo, *tHi, *tLo, *Wb16, *tgtT16, *Wm16, *PT16;
    float* srcT;
    cudaGetSymbolAddress((void**)&sHi, g_sHi);
    cudaGetSymbolAddress((void**)&sLo, g_sLo);
    cudaGetSymbolAddress((void**)&tHi, g_tHi);
    cudaGetSymbolAddress((void**)&tLo, g_tLo);
    cudaGetSymbolAddress((void**)&Wb16, g_Wb16);
    cudaGetSymbolAddress((void**)&tgtT16, g_tgtT16);
    cudaGetSymbolAddress((void**)&Wm16, g_Wm16);
    cudaGetSymbolAddress((void**)&PT16, g_PT16);
    cudaGetSymbolAddress((void**)&srcT, g_srcT);

    const int smemSplit = 3 * 2 * (TILE_A_B + TILE_B_B);  // 184320 (3 stages)
    const int smemPlain = 6 * (TILE_A_B + TILE_B_B);      // 184320 (6 stages)
    cudaFuncSetAttribute((const void*)gemm_hmma<0, true, 3>,
                         cudaFuncAttributeMaxDynamicSharedMemorySize, smemSplit);
    cudaFuncSetAttribute((const void*)gemm_hmma<1, false, 6>,
                         cudaFuncAttributeMaxDynamicSharedMemorySize, smemPlain);
    cudaFuncSetAttribute((const void*)gemm_hmma<2, false, 6>,
                         cudaFuncAttributeMaxDynamicSharedMemorySize, smemPlain);

    zero_kernel<<<1, 1>>>();
    sumsq_kernel<<<2048, NTH>>>(target);
    rowsum_kernel<<<P, NTH>>>(Wbeta);
    scale_kernel<<<P / NTH, NTH>>>();

    convert_split_kernel<<<1024, NTH>>>(source, sHi, sLo);
    convert_split_kernel<<<1024, NTH>>>(target, tHi, tLo);
    convert_plain_kernel<<<1024, NTH>>>(Wbeta, Wb16);
    dim3 tgrid(P / 32, P / 32), tblk(32, 8);
    transpose_bf16_kernel<<<tgrid, tblk>>>(target, tgtT16);
    transpose_f32_kernel<<<tgrid, tblk>>>(source, srcT);

    dim3 grid(P / BN, P / BM);  // 16 x 32 = 512 CTAs
    // GEMM1 (split): out[1+i*P+j] = scale[i]*sum_k src[i,k]*tgt[j,k]; Wm16 = bf16(same)
    gemm_hmma<0, true, 3><<<grid, NTH, smemSplit>>>(
        sHi, sLo, tHi, tLo, nullptr, out + 1, Wm16);
    // GEMM2 (plain): PT16[j,i] = bf16( sum_k tgtT[j,k]*Wm[i,k] - srcT[j,i] )
    gemm_hmma<1, false, 6><<<grid, NTH, smemPlain>>>(
        tgtT16, nullptr, Wm16, nullptr, srcT, nullptr, PT16);
    // GEMM3 (plain): g_ss += sum( (sum_k Wb[i,k]*PT[j,k])^2 )
    gemm_hmma<2, false, 6><<<grid, NTH, smemPlain>>>(
        Wb16, nullptr, PT16, nullptr, nullptr, nullptr, nullptr);

    final_kernel<<<1, 1>>>(out);
}

// round 13
// speedup vs baseline: 1.3939x; 1.3939x over previous
#include <cuda_runtime.h>
#include <cuda_bf16.h>
#include <cuda_fp16.h>
#include <cstdint>
#include <math.h>

#define P 4096
#define NTH 256
#define BM 128
#define BN 128
#define BKF 32                  // K elems per chunk
#define NCH (P / BKF)           // 128
#define LDT 40                  // padded smem row (bf16/fp16 elems) = 80B
#define TILE_B (128 * LDT * 2)  // 10240 B per operand tile

// ---------------------------------------------------------------- scratch
__device__ __half         g_sHi[(size_t)P * P];   // source hi (fp16)
__device__ __half         g_sLo[(size_t)P * P];   // source lo (fp16)
__device__ __half         g_tF16[(size_t)P * P];  // target (fp16, single)
__device__ __nv_bfloat16  g_Wb16[(size_t)P * P];
__device__ __nv_bfloat16  g_tgtT16[(size_t)P * P];
__device__ __nv_bfloat16  g_Wm16[(size_t)P * P];
__device__ __nv_bfloat16  g_PT16[(size_t)P * P];
__device__ float  g_srcT[(size_t)P * P];
__device__ float  g_W[P];
__device__ float  g_scale[P];
__device__ double g_s;
__device__ double g_ss;

// ---------------------------------------------------------------- helpers
__device__ __forceinline__ uint32_t smem_to_u32(const void* p) {
    uint32_t a;
    asm("{ .reg .u64 t; cvta.to.shared.u64 t, %1; cvt.u32.u64 %0, t; }" : "=r"(a) : "l"(p));
    return a;
}
__device__ __forceinline__ void ldsm4(uint32_t* r, uint32_t addr) {
    asm volatile("ldmatrix.sync.aligned.m8n8.x4.shared.b16 {%0,%1,%2,%3}, [%4];"
                 : "=r"(r[0]), "=r"(r[1]), "=r"(r[2]), "=r"(r[3]) : "r"(addr));
}
__device__ __forceinline__ void mma_bf16(float* d, const uint32_t* a, uint32_t b0, uint32_t b1) {
    asm volatile(
        "mma.sync.aligned.m16n8k16.row.col.f32.bf16.bf16.f32 "
        "{%0,%1,%2,%3}, {%4,%5,%6,%7}, {%8,%9}, {%0,%1,%2,%3};"
        : "+f"(d[0]), "+f"(d[1]), "+f"(d[2]), "+f"(d[3])
        : "r"(a[0]), "r"(a[1]), "r"(a[2]), "r"(a[3]), "r"(b0), "r"(b1));
}
__device__ __forceinline__ void mma_f16(float* d, const uint32_t* a, uint32_t b0, uint32_t b1) {
    asm volatile(
        "mma.sync.aligned.m16n8k16.row.col.f32.f16.f16.f32 "
        "{%0,%1,%2,%3}, {%4,%5,%6,%7}, {%8,%9}, {%0,%1,%2,%3};"
        : "+f"(d[0]), "+f"(d[1]), "+f"(d[2]), "+f"(d[3])
        : "r"(a[0]), "r"(a[1]), "r"(a[2]), "r"(a[3]), "r"(b0), "r"(b1));
}
#define CP_ASYNC16(dst, src) \
    asm volatile("cp.async.cg.shared.global [%0], [%1], 16;" :: "r"(dst), "l"(src) : "memory")
#define CP_COMMIT() asm volatile("cp.async.commit_group;" ::: "memory")

__device__ __forceinline__ uint32_t pack_bf16(float x, float y) {
    __nv_bfloat162 hb = __floats2bfloat162_rn(x, y);
    return *reinterpret_cast<uint32_t*>(&hb);
}

// ---------------------------------------------------------------- small kernels
__global__ void zero_kernel() { g_s = 0.0; g_ss = 0.0; }

__global__ void sumsq_kernel(const float* __restrict__ X) {
    __shared__ float sdata[NTH];
    float acc = 0.f;
    size_t n = (size_t)P * P;
    for (size_t i = (size_t)blockIdx.x * blockDim.x + threadIdx.x; i < n;
         i += (size_t)gridDim.x * blockDim.x) { float v = X[i]; acc += v * v; }
    sdata[threadIdx.x] = acc; __syncthreads();
    for (int s = NTH / 2; s > 0; s >>= 1) {
        if (threadIdx.x < s) sdata[threadIdx.x] += sdata[threadIdx.x + s];
        __syncthreads();
    }
    if (threadIdx.x == 0) atomicAdd(&g_s, (double)sdata[0]);
}

__global__ void rowsum_kernel(const float* __restrict__ Wb) {
    __shared__ float sdata[NTH];
    const float* rp = Wb + (size_t)blockIdx.x * P;
    float acc = 0.f;
    for (int j = threadIdx.x; j < P; j += NTH) acc += rp[j];
    sdata[threadIdx.x] = acc; __syncthreads();
    for (int s = NTH / 2; s > 0; s >>= 1) {
        if (threadIdx.x < s) sdata[threadIdx.x] += sdata[threadIdx.x + s];
        __syncthreads();
    }
    if (threadIdx.x == 0) g_W[blockIdx.x] = sdata[0];
}

__global__ void scale_kernel() {
    int i = blockIdx.x * blockDim.x + threadIdx.x;
    if (i < P) {
        float w = g_W[i], w2 = w * w;
        g_scale[i] = w2 / ((float)g_s * w2 + 1.0f);
    }
}

// f32 -> (hi, lo) fp16 arrays (A exact to ~22 bits)
__global__ void convert_split_f16_kernel(const float* __restrict__ in,
                                         __half* __restrict__ hi,
                                         __half* __restrict__ lo) {
    size_t n4 = (size_t)P * P / 4;
    for (size_t i = (size_t)blockIdx.x * blockDim.x + threadIdx.x; i < n4;
         i += (size_t)gridDim.x * blockDim.x) {
        float4 v = ((const float4*)in)[i];
        __half2 h01 = __floats2half2_rn(v.x, v.y);
        __half2 h23 = __floats2half2_rn(v.z, v.w);
        float2 f01 = __half22float2(h01);
        float2 f23 = __half22float2(h23);
        __half2 l01 = __floats2half2_rn(v.x - f01.x, v.y - f01.y);
        __half2 l23 = __floats2half2_rn(v.z - f23.x, v.w - f23.y);
        ((uint2*)hi)[i] = make_uint2(*(uint32_t*)&h01, *(uint32_t*)&h23);
        ((uint2*)lo)[i] = make_uint2(*(uint32_t*)&l01, *(uint32_t*)&l23);
    }
}

__global__ void convert_f16_kernel(const float* __restrict__ in,
                                   __half* __restrict__ o16) {
    size_t n4 = (size_t)P * P / 4;
    for (size_t i = (size_t)blockIdx.x * blockDim.x + threadIdx.x; i < n4;
         i += (size_t)gridDim.x * blockDim.x) {
        float4 v = ((const float4*)in)[i];
        __half2 h01 = __floats2half2_rn(v.x, v.y);
        __half2 h23 = __floats2half2_rn(v.z, v.w);
        ((uint2*)o16)[i] = make_uint2(*(uint32_t*)&h01, *(uint32_t*)&h23);
    }
}

__global__ void convert_plain_kernel(const float* __restrict__ in,
                                     __nv_bfloat16* __restrict__ o16) {
    size_t n4 = (size_t)P * P / 4;
    for (size_t i = (size_t)blockIdx.x * blockDim.x + threadIdx.x; i < n4;
         i += (size_t)gridDim.x * blockDim.x) {
        float4 v = ((const float4*)in)[i];
        ((uint2*)o16)[i] = make_uint2(pack_bf16(v.x, v.y), pack_bf16(v.z, v.w));
    }
}

__global__ void transpose_f32_kernel(const float* __restrict__ in, float* __restrict__ out) {
    __shared__ float tile[32][33];
    int x = blockIdx.x * 32 + threadIdx.x;
    int y0 = blockIdx.y * 32;
    for (int j = threadIdx.y; j < 32; j += 8)
        tile[j][threadIdx.x] = in[(size_t)(y0 + j) * P + x];
    __syncthreads();
    int x2 = blockIdx.y * 32 + threadIdx.x;
    int y2 = blockIdx.x * 32;
    for (int j = threadIdx.y; j < 32; j += 8)
        out[(size_t)(y2 + j) * P + x2] = tile[threadIdx.x][j];
}

__global__ void transpose_bf16_kernel(const float* __restrict__ in,
                                      __nv_bfloat16* __restrict__ out) {
    __shared__ float tile[32][33];
    int x = blockIdx.x * 32 + threadIdx.x;
    int y0 = blockIdx.y * 32;
    for (int j = threadIdx.y; j < 32; j += 8)
        tile[j][threadIdx.x] = in[(size_t)(y0 + j) * P + x];
    __syncthreads();
    int x2 = blockIdx.y * 32 + threadIdx.x;
    int y2 = blockIdx.x * 32;
    for (int j = threadIdx.y; j < 32; j += 8)
        out[(size_t)(y2 + j) * P + x2] = __float2bfloat16(tile[threadIdx.x][j]);
}

__global__ void final_kernel(float* __restrict__ out) { out[0] = (float)sqrt(g_ss); }

// ---------------------------------------------------------------- HMMA GEMM
// R8-exact geometry: CTA 128x128, 8 warps of 64x32, 2 CTAs/SM.
// SPLIT (fp16): 2 passes, D = Ah*B + Al*B (stage = 3 tiles: Ah, Al, B).
// plain (bf16): 1 pass (stage = 2 tiles: A, B).
// EPI 0: Cf32 = scale[r]*acc (scalar stores into 4B-aligned out), C16 = bf16(same)
// EPI 1: C16 = bf16(acc - Dg)
// EPI 2: g_ss += sum(acc^2)
template <int EPI, bool SPLIT, int NSTAGE, bool F16>
__global__ void __launch_bounds__(NTH, 2)
gemm_hmma(const uint16_t* __restrict__ Ah_, const uint16_t* __restrict__ Al_,
          const uint16_t* __restrict__ Bh_,
          const float* __restrict__ Dg, float* __restrict__ Cf32,
          __nv_bfloat16* __restrict__ C16) {
    extern __shared__ char smem[];
    const uint32_t su = smem_to_u32(smem);
    const int tid = threadIdx.x;
    const int lane = tid & 31;
    const int wid = tid >> 5;
    const int rowBase = blockIdx.y * BM;
    const int colBase = blockIdx.x * BN;
    const int m64 = (wid & 1) * 64;
    const int n32 = (wid >> 1) * 32;
    const uint32_t STAGE_B = (SPLIT ? 3 : 2) * TILE_B;
    const uint32_t bOff    = (SPLIT ? 2 : 1) * TILE_B;

    float acc[4][4][4];
#pragma unroll
    for (int i = 0; i < 4; i++)
#pragma unroll
        for (int j = 0; j < 4; j++)
#pragma unroll
            for (int q = 0; q < 4; q++) acc[i][j][q] = 0.f;

    // cp.async producer: 512 16B-transfers per tile; tiles [Ah,(Al),B]
    auto issue = [&](int chunk) {
        const uint32_t sb = su + (uint32_t)(chunk % NSTAGE) * STAGE_B;
        const int k0 = chunk * BKF;
        const int NT = SPLIT ? 6 : 4;
#pragma unroll
        for (int t = 0; t < NT; t++) {
            int idx = tid + t * NTH;
            int tile = idx >> 9;
            int within = idx & 511;
            int row = within >> 2, q = within & 3;
            const uint16_t* src;
            int gRow;
            if (SPLIT) {
                src = (tile == 0) ? Ah_ : (tile == 1) ? Al_ : Bh_;
                gRow = (tile < 2 ? rowBase : colBase) + row;
            } else {
                src = (tile == 0) ? Ah_ : Bh_;
                gRow = (tile == 0 ? rowBase : colBase) + row;
            }
            uint32_t dst = sb + (uint32_t)tile * TILE_B + row * (LDT * 2) + q * 16;
            CP_ASYNC16(dst, src + (size_t)gRow * P + k0 + q * 8);
        }
    };

    // ldmatrix lane addressing (byte offsets, row stride 80B) — validated R6-R8
    const int aRowOff = (lane & 7) + ((lane >> 3) & 1) * 8;
    const int aCbOff  = (lane >> 4) * 16;
    const int bRowOff = (lane & 7) + ((lane >> 4) & 1) * 8;
    const int bCbOff  = ((lane >> 3) & 1) * 16;

#pragma unroll
    for (int s = 0; s < NSTAGE - 1; s++) { issue(s); CP_COMMIT(); }

#pragma unroll 1
    for (int c = 0; c < NCH; c++) {
        if (c + NSTAGE - 1 < NCH) issue(c + NSTAGE - 1);
        CP_COMMIT();
        asm volatile("cp.async.wait_group %0;" :: "n"(NSTAGE - 1) : "memory");
        __syncthreads();

        const uint32_t sb = su + (uint32_t)(c % NSTAGE) * STAGE_B;
        const uint32_t aH = sb, aL = sb + TILE_B;
        const uint32_t bH = sb + bOff;

        const int npass = SPLIT ? 2 : 1;
#pragma unroll
        for (int pass = 0; pass < npass; pass++) {
            uint32_t aBase = pass ? aL : aH;   // Ah*B, Al*B
            uint32_t bBase = bH;
#pragma unroll
            for (int ks = 0; ks < 2; ks++) {
                uint32_t af[4][4], bf[2][4];
#pragma unroll
                for (int mi = 0; mi < 4; mi++)
                    ldsm4(af[mi], aBase + (m64 + mi * 16 + aRowOff) * (LDT * 2) + ks * 32 + aCbOff);
#pragma unroll
                for (int np = 0; np < 2; np++)
                    ldsm4(bf[np], bBase + (n32 + np * 16 + bRowOff) * (LDT * 2) + ks * 32 + bCbOff);
#pragma unroll
                for (int mi = 0; mi < 4; mi++)
#pragma unroll
                    for (int np = 0; np < 2; np++) {
                        if (F16) {
                            mma_f16(acc[mi][np * 2 + 0], af[mi], bf[np][0], bf[np][1]);
                            mma_f16(acc[mi][np * 2 + 1], af[mi], bf[np][2], bf[np][3]);
                        } else {
                            mma_bf16(acc[mi][np * 2 + 0], af[mi], bf[np][0], bf[np][1]);
                            mma_bf16(acc[mi][np * 2 + 1], af[mi], bf[np][2], bf[np][3]);
                        }
                    }
            }
        }
        __syncthreads();
    }

    // ---------------- epilogue ----------------
    const int rq = lane >> 2;
    const int cq = (lane & 3) * 2;
    float locss = 0.f;
#pragma unroll
    for (int mi = 0; mi < 4; mi++) {
        int r0 = rowBase + m64 + mi * 16 + rq;
        int r1 = r0 + 8;
        float s0 = 0.f, s1 = 0.f;
        if (EPI == 0) { s0 = g_scale[r0]; s1 = g_scale[r1]; }
#pragma unroll
        for (int ni = 0; ni < 4; ni++) {
            int cg = colBase + n32 + ni * 8 + cq;
            float* d = acc[mi][ni];
            if (EPI == 0) {
                float v0 = s0 * d[0], v1 = s0 * d[1];
                float v2 = s1 * d[2], v3 = s1 * d[3];
                Cf32[(size_t)r0 * P + cg]     = v0;
                Cf32[(size_t)r0 * P + cg + 1] = v1;
                Cf32[(size_t)r1 * P + cg]     = v2;
                Cf32[(size_t)r1 * P + cg + 1] = v3;
                *(uint32_t*)(C16 + (size_t)r0 * P + cg) = pack_bf16(v0, v1);
                *(uint32_t*)(C16 + (size_t)r1 * P + cg) = pack_bf16(v2, v3);
            } else if (EPI == 1) {
                float2 x0 = *(const float2*)(Dg + (size_t)r0 * P + cg);
                float2 x1 = *(const float2*)(Dg + (size_t)r1 * P + cg);
                *(uint32_t*)(C16 + (size_t)r0 * P + cg) = pack_bf16(d[0] - x0.x, d[1] - x0.y);
                *(uint32_t*)(C16 + (size_t)r1 * P + cg) = pack_bf16(d[2] - x1.x, d[3] - x1.y);
            } else {
                locss += d[0] * d[0] + d[1] * d[1] + d[2] * d[2] + d[3] * d[3];
            }
        }
    }
    if (EPI == 2) {
        __syncthreads();
        float* red = (float*)smem;
        red[tid] = locss;
        __syncthreads();
        for (int s = NTH / 2; s > 0; s >>= 1) {
            if (tid < s) red[tid] += red[tid + s];
            __syncthreads();
        }
        if (tid == 0) atomicAdd(&g_ss, (double)red[0]);
    }
}

// ---------------------------------------------------------------- launch
extern "C" void kernel_launch(void* const* d_in, const int* in_sizes, int n_in,
                              void* d_out, int out_size) {
    const float* target = (const float*)d_in[0];
    const float* source = (const float*)d_in[1];
    const float* Wbeta  = (const float*)d_in[2];
    float* out = (float*)d_out;   // out[0]=loss, out[1:]=W_matrix

    __half *sHi, *sLo, *tF16;
    __nv_bfloat16 *Wb16, *tgtT16, *Wm16, *PT16;
    float* srcT;
    cudaGetSymbolAddress((void**)&sHi, g_sHi);
    cudaGetSymbolAddress((void**)&sLo, g_sLo);
    cudaGetSymbolAddress((void**)&tF16, g_tF16);
    cudaGetSymbolAddress((void**)&Wb16, g_Wb16);
    cudaGetSymbolAddress((void**)&tgtT16, g_tgtT16);
    cudaGetSymbolAddress((void**)&Wm16, g_Wm16);
    cudaGetSymbolAddress((void**)&PT16, g_PT16);
    cudaGetSymbolAddress((void**)&srcT, g_srcT);

    const int smemSplit = 3 * 3 * TILE_B;   // 92160 (3 stages x 3 tiles), 2 CTAs/SM
    const int smemPlain = 4 * 2 * TILE_B;   // 81920 (4 stages x 2 tiles), 2 CTAs/SM
    cudaFuncSetAttribute((const void*)gemm_hmma<0, true, 3, true>,
                         cudaFuncAttributeMaxDynamicSharedMemorySize, smemSplit);
    cudaFuncSetAttribute((const void*)gemm_hmma<1, false, 4, false>,
                         cudaFuncAttributeMaxDynamicSharedMemorySize, smemPlain);
    cudaFuncSetAttribute((const void*)gemm_hmma<2, false, 4, false>,
                         cudaFuncAttributeMaxDynamicSharedMemorySize, smemPlain);

    zero_kernel<<<1, 1>>>();
    sumsq_kernel<<<2048, NTH>>>(target);
    rowsum_kernel<<<P, NTH>>>(Wbeta);
    scale_kernel<<<P / NTH, NTH>>>();

    convert_split_f16_kernel<<<1024, NTH>>>(source, sHi, sLo);
    convert_f16_kernel<<<1024, NTH>>>(target, tF16);
    convert_plain_kernel<<<1024, NTH>>>(Wbeta, Wb16);
    dim3 tgrid(P / 32, P / 32), tblk(32, 8);
    transpose_bf16_kernel<<<tgrid, tblk>>>(target, tgtT16);
    transpose_f32_kernel<<<tgrid, tblk>>>(source, srcT);

    dim3 grid(P / BN, P / BM);  // 32 x 32
    // GEMM1 (fp16, A-split 2-pass): out[1+i*P+j] = scale[i]*sum_k src[i,k]*tgt[j,k]
    gemm_hmma<0, true, 3, true><<<grid, NTH, smemSplit>>>(
        (const uint16_t*)sHi, (const uint16_t*)sLo, (const uint16_t*)tF16,
        nullptr, out + 1, Wm16);
    // GEMM2 (bf16 plain): PT16[j,i] = bf16( sum_k tgtT[j,k]*Wm[i,k] - srcT[j,i] )
    gemm_hmma<1, false, 4, false><<<grid, NTH, smemPlain>>>(
        (const uint16_t*)tgtT16, nullptr, (const uint16_t*)Wm16,
        srcT, nullptr, PT16);
    // GEMM3 (bf16 plain): g_ss += sum( (sum_k Wb[i,k]*PT[j,k])^2 )
    gemm_hmma<2, false, 4, false><<<grid, NTH, smemPlain>>>(
        (const uint16_t*)Wb16, nullptr, (const uint16_t*)PT16,
        nullptr, nullptr, nullptr);

    final_kernel<<<1, 1>>>(out);
}

// round 15
// speedup vs baseline: 1.6642x; 1.1939x over previous
#include <cuda_runtime.h>
#include <cuda_bf16.h>
#include <cuda_fp16.h>
#include <cstdint>
#include <math.h>

#define P 4096
#define NTH 256
#define BM 128
#define BN 128
#define BKF 32                  // K elems per chunk
#define NCH (P / BKF)           // 128
#define LDT 40                  // padded smem row (16-bit elems) = 80B
#define TILE_B (128 * LDT * 2)  // 10240 B per operand tile

// ---------------------------------------------------------------- scratch
__device__ __half         g_sF16[(size_t)P * P];  // source (fp16)
__device__ __half         g_tF16[(size_t)P * P];  // target (fp16)
__device__ __nv_bfloat16  g_Wb16[(size_t)P * P];
__device__ __nv_bfloat16  g_tgtT16[(size_t)P * P];
__device__ __nv_bfloat16  g_Wm16[(size_t)P * P];  // bf16: Wm ~4e-6 is fp16-subnormal!
__device__ __nv_bfloat16  g_PT16[(size_t)P * P];
__device__ float  g_srcT[(size_t)P * P];
__device__ float  g_W[P];
__device__ float  g_scale[P];
__device__ double g_s;
__device__ double g_ss;

// ---------------------------------------------------------------- helpers
__device__ __forceinline__ uint32_t smem_to_u32(const void* p) {
    uint32_t a;
    asm("{ .reg .u64 t; cvta.to.shared.u64 t, %1; cvt.u32.u64 %0, t; }" : "=r"(a) : "l"(p));
    return a;
}
__device__ __forceinline__ void ldsm4(uint32_t* r, uint32_t addr) {
    asm volatile("ldmatrix.sync.aligned.m8n8.x4.shared.b16 {%0,%1,%2,%3}, [%4];"
                 : "=r"(r[0]), "=r"(r[1]), "=r"(r[2]), "=r"(r[3]) : "r"(addr));
}
__device__ __forceinline__ void mma_bf16(float* d, const uint32_t* a, uint32_t b0, uint32_t b1) {
    asm volatile(
        "mma.sync.aligned.m16n8k16.row.col.f32.bf16.bf16.f32 "
        "{%0,%1,%2,%3}, {%4,%5,%6,%7}, {%8,%9}, {%0,%1,%2,%3};"
        : "+f"(d[0]), "+f"(d[1]), "+f"(d[2]), "+f"(d[3])
        : "r"(a[0]), "r"(a[1]), "r"(a[2]), "r"(a[3]), "r"(b0), "r"(b1));
}
__device__ __forceinline__ void mma_f16(float* d, const uint32_t* a, uint32_t b0, uint32_t b1) {
    asm volatile(
        "mma.sync.aligned.m16n8k16.row.col.f32.f16.f16.f32 "
        "{%0,%1,%2,%3}, {%4,%5,%6,%7}, {%8,%9}, {%0,%1,%2,%3};"
        : "+f"(d[0]), "+f"(d[1]), "+f"(d[2]), "+f"(d[3])
        : "r"(a[0]), "r"(a[1]), "r"(a[2]), "r"(a[3]), "r"(b0), "r"(b1));
}
#define CP_ASYNC16(dst, src) \
    asm volatile("cp.async.cg.shared.global [%0], [%1], 16;" :: "r"(dst), "l"(src) : "memory")
#define CP_COMMIT() asm volatile("cp.async.commit_group;" ::: "memory")

__device__ __forceinline__ uint32_t pack_bf16(float x, float y) {
    __nv_bfloat162 hb = __floats2bfloat162_rn(x, y);
    return *reinterpret_cast<uint32_t*>(&hb);
}

// ---------------------------------------------------------------- small kernels
__global__ void zero_kernel() { g_s = 0.0; g_ss = 0.0; }

__global__ void sumsq_kernel(const float* __restrict__ X) {
    __shared__ float sdata[NTH];
    float acc = 0.f;
    size_t n = (size_t)P * P;
    for (size_t i = (size_t)blockIdx.x * blockDim.x + threadIdx.x; i < n;
         i += (size_t)gridDim.x * blockDim.x) { float v = X[i]; acc += v * v; }
    sdata[threadIdx.x] = acc; __syncthreads();
    for (int s = NTH / 2; s > 0; s >>= 1) {
        if (threadIdx.x < s) sdata[threadIdx.x] += sdata[threadIdx.x + s];
        __syncthreads();
    }
    if (threadIdx.x == 0) atomicAdd(&g_s, (double)sdata[0]);
}

__global__ void rowsum_kernel(const float* __restrict__ Wb) {
    __shared__ float sdata[NTH];
    const float* rp = Wb + (size_t)blockIdx.x * P;
    float acc = 0.f;
    for (int j = threadIdx.x; j < P; j += NTH) acc += rp[j];
    sdata[threadIdx.x] = acc; __syncthreads();
    for (int s = NTH / 2; s > 0; s >>= 1) {
        if (threadIdx.x < s) sdata[threadIdx.x] += sdata[threadIdx.x + s];
        __syncthreads();
    }
    if (threadIdx.x == 0) g_W[blockIdx.x] = sdata[0];
}

__global__ void scale_kernel() {
    int i = blockIdx.x * blockDim.x + threadIdx.x;
    if (i < P) {
        float w = g_W[i], w2 = w * w;
        g_scale[i] = w2 / ((float)g_s * w2 + 1.0f);
    }
}

__global__ void convert_f16_kernel(const float* __restrict__ in,
                                   __half* __restrict__ o16) {
    size_t n4 = (size_t)P * P / 4;
    for (size_t i = (size_t)blockIdx.x * blockDim.x + threadIdx.x; i < n4;
         i += (size_t)gridDim.x * blockDim.x) {
        float4 v = ((const float4*)in)[i];
        __half2 h01 = __floats2half2_rn(v.x, v.y);
        __half2 h23 = __floats2half2_rn(v.z, v.w);
        ((uint2*)o16)[i] = make_uint2(*(uint32_t*)&h01, *(uint32_t*)&h23);
    }
}

__global__ void convert_plain_kernel(const float* __restrict__ in,
                                     __nv_bfloat16* __restrict__ o16) {
    size_t n4 = (size_t)P * P / 4;
    for (size_t i = (size_t)blockIdx.x * blockDim.x + threadIdx.x; i < n4;
         i += (size_t)gridDim.x * blockDim.x) {
        float4 v = ((const float4*)in)[i];
        ((uint2*)o16)[i] = make_uint2(pack_bf16(v.x, v.y), pack_bf16(v.z, v.w));
    }
}

__global__ void transpose_f32_kernel(const float* __restrict__ in, float* __restrict__ out) {
    __shared__ float tile[32][33];
    int x = blockIdx.x * 32 + threadIdx.x;
    int y0 = blockIdx.y * 32;
    for (int j = threadIdx.y; j < 32; j += 8)
        tile[j][threadIdx.x] = in[(size_t)(y0 + j) * P + x];
    __syncthreads();
    int x2 = blockIdx.y * 32 + threadIdx.x;
    int y2 = blockIdx.x * 32;
    for (int j = threadIdx.y; j < 32; j += 8)
        out[(size_t)(y2 + j) * P + x2] = tile[threadIdx.x][j];
}

__global__ void transpose_bf16_kernel(const float* __restrict__ in,
                                      __nv_bfloat16* __restrict__ out) {
    __shared__ float tile[32][33];
    int x = blockIdx.x * 32 + threadIdx.x;
    int y0 = blockIdx.y * 32;
    for (int j = threadIdx.y; j < 32; j += 8)
        tile[j][threadIdx.x] = in[(size_t)(y0 + j) * P + x];
    __syncthreads();
    int x2 = blockIdx.y * 32 + threadIdx.x;
    int y2 = blockIdx.x * 32;
    for (int j = threadIdx.y; j < 32; j += 8)
        out[(size_t)(y2 + j) * P + x2] = __float2bfloat16(tile[threadIdx.x][j]);
}

__global__ void final_kernel(float* __restrict__ out) { out[0] = (float)sqrt(g_ss); }

// ---------------------------------------------------------------- HMMA GEMM
// Proven geometry: CTA 128x128, 8 warps of 64x32, 2 CTAs/SM, NSTAGE=4, 1 pass.
// F16 selects fp16 vs bf16 MMA (operand arrays are both 16-bit, passed as u16*).
// EPI 0: Cf32 = scale[r]*acc (scalar stores into 4B-aligned out), C16 = bf16(same)
// EPI 1: C16 = bf16(acc - Dg)
// EPI 2: g_ss += sum(acc^2)
template <int EPI, int NSTAGE, bool F16>
__global__ void __launch_bounds__(NTH, 2)
gemm_hmma(const uint16_t* __restrict__ A_, const uint16_t* __restrict__ B_,
          const float* __restrict__ Dg, float* __restrict__ Cf32,
          __nv_bfloat16* __restrict__ C16) {
    extern __shared__ char smem[];
    const uint32_t su = smem_to_u32(smem);
    const int tid = threadIdx.x;
    const int lane = tid & 31;
    const int wid = tid >> 5;
    const int rowBase = blockIdx.y * BM;
    const int colBase = blockIdx.x * BN;
    const int m64 = (wid & 1) * 64;
    const int n32 = (wid >> 1) * 32;
    const uint32_t STAGE_B = 2 * TILE_B;

    float acc[4][4][4];
#pragma unroll
    for (int i = 0; i < 4; i++)
#pragma unroll
        for (int j = 0; j < 4; j++)
#pragma unroll
            for (int q = 0; q < 4; q++) acc[i][j][q] = 0.f;

    // cp.async producer: 512 16B-transfers per tile; tiles [A, B]
    auto issue = [&](int chunk) {
        const uint32_t sb = su + (uint32_t)(chunk % NSTAGE) * STAGE_B;
        const int k0 = chunk * BKF;
#pragma unroll
        for (int t = 0; t < 4; t++) {
            int idx = tid + t * NTH;
            int tile = idx >> 9;
            int within = idx & 511;
            int row = within >> 2, q = within & 3;
            const uint16_t* src = (tile == 0) ? A_ : B_;
            int gRow = (tile == 0 ? rowBase : colBase) + row;
            uint32_t dst = sb + (uint32_t)tile * TILE_B + row * (LDT * 2) + q * 16;
            CP_ASYNC16(dst, src + (size_t)gRow * P + k0 + q * 8);
        }
    };

    // ldmatrix lane addressing (byte offsets, row stride 80B) — validated R6-R13
    const int aRowOff = (lane & 7) + ((lane >> 3) & 1) * 8;
    const int aCbOff  = (lane >> 4) * 16;
    const int bRowOff = (lane & 7) + ((lane >> 4) & 1) * 8;
    const int bCbOff  = ((lane >> 3) & 1) * 16;

#pragma unroll
    for (int s = 0; s < NSTAGE - 1; s++) { issue(s); CP_COMMIT(); }

#pragma unroll 1
    for (int c = 0; c < NCH; c++) {
        if (c + NSTAGE - 1 < NCH) issue(c + NSTAGE - 1);
        CP_COMMIT();
        asm volatile("cp.async.wait_group %0;" :: "n"(NSTAGE - 1) : "memory");
        __syncthreads();

        const uint32_t sb = su + (uint32_t)(c % NSTAGE) * STAGE_B;
        const uint32_t aBase = sb, bBase = sb + TILE_B;

#pragma unroll
        for (int ks = 0; ks < 2; ks++) {
            uint32_t af[4][4], bf[2][4];
#pragma unroll
            for (int mi = 0; mi < 4; mi++)
                ldsm4(af[mi], aBase + (m64 + mi * 16 + aRowOff) * (LDT * 2) + ks * 32 + aCbOff);
#pragma unroll
            for (int np = 0; np < 2; np++)
                ldsm4(bf[np], bBase + (n32 + np * 16 + bRowOff) * (LDT * 2) + ks * 32 + bCbOff);
#pragma unroll
            for (int mi = 0; mi < 4; mi++)
#pragma unroll
                for (int np = 0; np < 2; np++) {
                    if (F16) {
                        mma_f16(acc[mi][np * 2 + 0], af[mi], bf[np][0], bf[np][1]);
                        mma_f16(acc[mi][np * 2 + 1], af[mi], bf[np][2], bf[np][3]);
                    } else {
                        mma_bf16(acc[mi][np * 2 + 0], af[mi], bf[np][0], bf[np][1]);
                        mma_bf16(acc[mi][np * 2 + 1], af[mi], bf[np][2], bf[np][3]);
                    }
                }
        }
        __syncthreads();
    }

    // ---------------- epilogue ----------------
    const int rq = lane >> 2;
    const int cq = (lane & 3) * 2;
    float locss = 0.f;
#pragma unroll
    for (int mi = 0; mi < 4; mi++) {
        int r0 = rowBase + m64 + mi * 16 + rq;
        int r1 = r0 + 8;
        float s0 = 0.f, s1 = 0.f;
        if (EPI == 0) { s0 = g_scale[r0]; s1 = g_scale[r1]; }
#pragma unroll
        for (int ni = 0; ni < 4; ni++) {
            int cg = colBase + n32 + ni * 8 + cq;
            float* d = acc[mi][ni];
            if (EPI == 0) {
                float v0 = s0 * d[0], v1 = s0 * d[1];
                float v2 = s1 * d[2], v3 = s1 * d[3];
                Cf32[(size_t)r0 * P + cg]     = v0;
                Cf32[(size_t)r0 * P + cg + 1] = v1;
                Cf32[(size_t)r1 * P + cg]     = v2;
                Cf32[(size_t)r1 * P + cg + 1] = v3;
                *(uint32_t*)(C16 + (size_t)r0 * P + cg) = pack_bf16(v0, v1);
                *(uint32_t*)(C16 + (size_t)r1 * P + cg) = pack_bf16(v2, v3);
            } else if (EPI == 1) {
                float2 x0 = *(const float2*)(Dg + (size_t)r0 * P + cg);
                float2 x1 = *(const float2*)(Dg + (size_t)r1 * P + cg);
                *(uint32_t*)(C16 + (size_t)r0 * P + cg) = pack_bf16(d[0] - x0.x, d[1] - x0.y);
                *(uint32_t*)(C16 + (size_t)r1 * P + cg) = pack_bf16(d[2] - x1.x, d[3] - x1.y);
            } else {
                locss += d[0] * d[0] + d[1] * d[1] + d[2] * d[2] + d[3] * d[3];
            }
        }
    }
    if (EPI == 2) {
        __syncthreads();
        float* red = (float*)smem;
        red[tid] = locss;
        __syncthreads();
        for (int s = NTH / 2; s > 0; s >>= 1) {
            if (tid < s) red[tid] += red[tid + s];
            __syncthreads();
        }
        if (tid == 0) atomicAdd(&g_ss, (double)red[0]);
    }
}

// ---------------------------------------------------------------- launch
extern "C" void kernel_launch(void* const* d_in, const int* in_sizes, int n_in,
                              void* d_out, int out_size) {
    const float* target = (const float*)d_in[0];
    const float* source = (const float*)d_in[1];
    const float* Wbeta  = (const float*)d_in[2];
    float* out = (float*)d_out;   // out[0]=loss, out[1:]=W_matrix

    __half *sF16, *tF16;
    __nv_bfloat16 *Wb16, *tgtT16, *Wm16, *PT16;
    float* srcT;
    cudaGetSymbolAddress((void**)&sF16, g_sF16);
    cudaGetSymbolAddress((void**)&tF16, g_tF16);
    cudaGetSymbolAddress((void**)&Wb16, g_Wb16);
    cudaGetSymbolAddress((void**)&tgtT16, g_tgtT16);
    cudaGetSymbolAddress((void**)&Wm16, g_Wm16);
    cudaGetSymbolAddress((void**)&PT16, g_PT16);
    cudaGetSymbolAddress((void**)&srcT, g_srcT);

    const int smemGemm = 4 * 2 * TILE_B;   // 81920 (4 stages x 2 tiles), 2 CTAs/SM
    cudaFuncSetAttribute((const void*)gemm_hmma<0, 4, true>,
                         cudaFuncAttributeMaxDynamicSharedMemorySize, smemGemm);
    cudaFuncSetAttribute((const void*)gemm_hmma<1, 4, false>,
                         cudaFuncAttributeMaxDynamicSharedMemorySize, smemGemm);
    cudaFuncSetAttribute((const void*)gemm_hmma<2, 4, false>,
                         cudaFuncAttributeMaxDynamicSharedMemorySize, smemGemm);

    zero_kernel<<<1, 1>>>();
    sumsq_kernel<<<2048, NTH>>>(target);
    rowsum_kernel<<<P, NTH>>>(Wbeta);
    scale_kernel<<<P / NTH, NTH>>>();

    convert_f16_kernel<<<1024, NTH>>>(source, sF16);
    convert_f16_kernel<<<1024, NTH>>>(target, tF16);
    convert_plain_kernel<<<1024, NTH>>>(Wbeta, Wb16);
    dim3 tgrid(P / 32, P / 32), tblk(32, 8);
    transpose_bf16_kernel<<<tgrid, tblk>>>(target, tgtT16);
    transpose_f32_kernel<<<tgrid, tblk>>>(source, srcT);

    dim3 grid(P / BN, P / BM);  // 32 x 32
    // GEMM1 (fp16 single-pass): out[1+i*P+j] = scale[i]*sum_k src[i,k]*tgt[j,k]
    gemm_hmma<0, 4, true><<<grid, NTH, smemGemm>>>(
        (const uint16_t*)sF16, (const uint16_t*)tF16, nullptr, out + 1, Wm16);
    // GEMM2 (bf16; Wm ~4e-6 needs bf16 exponent range): PT16[j,i] = bf16(tgtT·Wm^T - srcT)
    gemm_hmma<1, 4, false><<<grid, NTH, smemGemm>>>(
        (const uint16_t*)tgtT16, (const uint16_t*)Wm16, srcT, nullptr, PT16);
    // GEMM3 (bf16): g_ss += sum( (Wb @ PT^T)^2 )
    gemm_hmma<2, 4, false><<<grid, NTH, smemGemm>>>(
        (const uint16_t*)Wb16, (const uint16_t*)PT16, nullptr, nullptr, nullptr);

    final_kernel<<<1, 1>>>(out);
}

// round 16
// speedup vs baseline: 1.7406x; 1.0459x over previous
#include <cuda_runtime.h>
#include <cuda_bf16.h>
#include <cuda_fp16.h>
#include <cstdint>
#include <math.h>

#define P 4096
#define NTH 256
#define BM 128
#define BN 128
#define BKF 32                  // K elems per chunk
#define NCH (P / BKF)           // 128
#define LDT 40                  // padded smem row (16-bit elems) = 80B
#define TILE_B (128 * LDT * 2)  // 10240 B per operand tile

// ---------------------------------------------------------------- scratch
__device__ __half         g_sF16[(size_t)P * P];   // source (fp16)
__device__ __half         g_tF16[(size_t)P * P];   // target (fp16)
__device__ __nv_bfloat16  g_Wb16[(size_t)P * P];
__device__ __nv_bfloat16  g_tgtT16[(size_t)P * P];
__device__ __nv_bfloat16  g_srcT16[(size_t)P * P]; // source^T (bf16)
__device__ __nv_bfloat16  g_Wm16[(size_t)P * P];   // bf16: Wm ~4e-6 is fp16-subnormal!
__device__ __nv_bfloat16  g_PT16[(size_t)P * P];
__device__ float  g_W[P];
__device__ float  g_scale[P];
__device__ double g_s;
__device__ double g_ss;

// ---------------------------------------------------------------- helpers
__device__ __forceinline__ uint32_t smem_to_u32(const void* p) {
    uint32_t a;
    asm("{ .reg .u64 t; cvta.to.shared.u64 t, %1; cvt.u32.u64 %0, t; }" : "=r"(a) : "l"(p));
    return a;
}
__device__ __forceinline__ void ldsm4(uint32_t* r, uint32_t addr) {
    asm volatile("ldmatrix.sync.aligned.m8n8.x4.shared.b16 {%0,%1,%2,%3}, [%4];"
                 : "=r"(r[0]), "=r"(r[1]), "=r"(r[2]), "=r"(r[3]) : "r"(addr));
}
__device__ __forceinline__ void mma_bf16(float* d, const uint32_t* a, uint32_t b0, uint32_t b1) {
    asm volatile(
        "mma.sync.aligned.m16n8k16.row.col.f32.bf16.bf16.f32 "
        "{%0,%1,%2,%3}, {%4,%5,%6,%7}, {%8,%9}, {%0,%1,%2,%3};"
        : "+f"(d[0]), "+f"(d[1]), "+f"(d[2]), "+f"(d[3])
        : "r"(a[0]), "r"(a[1]), "r"(a[2]), "r"(a[3]), "r"(b0), "r"(b1));
}
__device__ __forceinline__ void mma_f16(float* d, const uint32_t* a, uint32_t b0, uint32_t b1) {
    asm volatile(
        "mma.sync.aligned.m16n8k16.row.col.f32.f16.f16.f32 "
        "{%0,%1,%2,%3}, {%4,%5,%6,%7}, {%8,%9}, {%0,%1,%2,%3};"
        : "+f"(d[0]), "+f"(d[1]), "+f"(d[2]), "+f"(d[3])
        : "r"(a[0]), "r"(a[1]), "r"(a[2]), "r"(a[3]), "r"(b0), "r"(b1));
}
#define CP_ASYNC16(dst, src) \
    asm volatile("cp.async.cg.shared.global [%0], [%1], 16;" :: "r"(dst), "l"(src) : "memory")
#define CP_COMMIT() asm volatile("cp.async.commit_group;" ::: "memory")

__device__ __forceinline__ uint32_t pack_bf16(float x, float y) {
    __nv_bfloat162 hb = __floats2bfloat162_rn(x, y);
    return *reinterpret_cast<uint32_t*>(&hb);
}

// ---------------------------------------------------------------- small kernels
__global__ void zero_kernel() { g_s = 0.0; g_ss = 0.0; }

// One read of target -> tF16 (straight fp16) + tgtT16 (transposed bf16) + sumsq
__global__ void prep_target_kernel(const float* __restrict__ in,
                                   __half* __restrict__ o16,
                                   __nv_bfloat16* __restrict__ oT) {
    __shared__ float tile[32][33];
    __shared__ float red[NTH];
    int x = blockIdx.x * 32 + threadIdx.x;
    int y0 = blockIdx.y * 32;
    float ss = 0.f;
    for (int j = threadIdx.y; j < 32; j += 8) {
        float v = in[(size_t)(y0 + j) * P + x];
        tile[j][threadIdx.x] = v;
        ss += v * v;
        o16[(size_t)(y0 + j) * P + x] = __float2half_rn(v);
    }
    int tid = threadIdx.y * 32 + threadIdx.x;
    red[tid] = ss;
    __syncthreads();
    for (int s = NTH / 2; s > 0; s >>= 1) {
        if (tid < s) red[tid] += red[tid + s];
        __syncthreads();
    }
    if (tid == 0) atomicAdd(&g_s, (double)red[0]);
    int x2 = blockIdx.y * 32 + threadIdx.x;
    int y2 = blockIdx.x * 32;
    for (int j = threadIdx.y; j < 32; j += 8)
        oT[(size_t)(y2 + j) * P + x2] = __float2bfloat16(tile[threadIdx.x][j]);
}

// One read of source -> sF16 (straight fp16) + srcT16 (transposed bf16)
__global__ void prep_source_kernel(const float* __restrict__ in,
                                   __half* __restrict__ o16,
                                   __nv_bfloat16* __restrict__ oT) {
    __shared__ float tile[32][33];
    int x = blockIdx.x * 32 + threadIdx.x;
    int y0 = blockIdx.y * 32;
    for (int j = threadIdx.y; j < 32; j += 8) {
        float v = in[(size_t)(y0 + j) * P + x];
        tile[j][threadIdx.x] = v;
        o16[(size_t)(y0 + j) * P + x] = __float2half_rn(v);
    }
    __syncthreads();
    int x2 = blockIdx.y * 32 + threadIdx.x;
    int y2 = blockIdx.x * 32;
    for (int j = threadIdx.y; j < 32; j += 8)
        oT[(size_t)(y2 + j) * P + x2] = __float2bfloat16(tile[threadIdx.x][j]);
}

// One read of Wbeta -> Wb16 + row sums (one warp per row, 8 rows per block)
__global__ void prep_wbeta_kernel(const float* __restrict__ Wb,
                                  __nv_bfloat16* __restrict__ o16) {
    int row = blockIdx.x * 8 + threadIdx.y;
    const float* rp = Wb + (size_t)row * P;
    float acc = 0.f;
#pragma unroll 4
    for (int it = 0; it < 32; it++) {
        int col = it * 128 + threadIdx.x * 4;
        float4 v = *(const float4*)(rp + col);
        acc += (v.x + v.y) + (v.z + v.w);
        *(uint2*)(o16 + (size_t)row * P + col) =
            make_uint2(pack_bf16(v.x, v.y), pack_bf16(v.z, v.w));
    }
#pragma unroll
    for (int o = 16; o > 0; o >>= 1) acc += __shfl_xor_sync(0xFFFFFFFFu, acc, o);
    if (threadIdx.x == 0) g_W[row] = acc;
}

__global__ void scale_kernel() {
    int i = blockIdx.x * blockDim.x + threadIdx.x;
    if (i < P) {
        float w = g_W[i], w2 = w * w;
        g_scale[i] = w2 / ((float)g_s * w2 + 1.0f);
    }
}

__global__ void final_kernel(float* __restrict__ out) { out[0] = (float)sqrt(g_ss); }

// ---------------------------------------------------------------- HMMA GEMM
// Proven geometry: CTA 128x128, 8 warps of 64x32, 2 CTAs/SM, NSTAGE=4, 1 pass.
// F16 selects fp16 vs bf16 MMA (operand arrays are both 16-bit, passed as u16*).
// EPI 0: Cf32 = scale[r]*acc (scalar stores into 4B-aligned out), C16 = bf16(same)
// EPI 1: C16 = bf16(acc - Dg16)   (Dg16 = bf16 source^T)
// EPI 2: g_ss += sum(acc^2)
template <int EPI, int NSTAGE, bool F16>
__global__ void __launch_bounds__(NTH, 2)
gemm_hmma(const uint16_t* __restrict__ A_, const uint16_t* __restrict__ B_,
          const __nv_bfloat16* __restrict__ Dg16, float* __restrict__ Cf32,
          __nv_bfloat16* __restrict__ C16) {
    extern __shared__ char smem[];
    const uint32_t su = smem_to_u32(smem);
    const int tid = threadIdx.x;
    const int lane = tid & 31;
    const int wid = tid >> 5;
    const int rowBase = blockIdx.y * BM;
    const int colBase = blockIdx.x * BN;
    const int m64 = (wid & 1) * 64;
    const int n32 = (wid >> 1) * 32;
    const uint32_t STAGE_B = 2 * TILE_B;

    float acc[4][4][4];
#pragma unroll
    for (int i = 0; i < 4; i++)
#pragma unroll
        for (int j = 0; j < 4; j++)
#pragma unroll
            for (int q = 0; q < 4; q++) acc[i][j][q] = 0.f;

    // cp.async producer: 512 16B-transfers per tile; tiles [A, B]
    auto issue = [&](int chunk) {
        const uint32_t sb = su + (uint32_t)(chunk % NSTAGE) * STAGE_B;
        const int k0 = chunk * BKF;
#pragma unroll
        for (int t = 0; t < 4; t++) {
            int idx = tid + t * NTH;
            int tile = idx >> 9;
            int within = idx & 511;
            int row = within >> 2, q = within & 3;
            const uint16_t* src = (tile == 0) ? A_ : B_;
            int gRow = (tile == 0 ? rowBase : colBase) + row;
            uint32_t dst = sb + (uint32_t)tile * TILE_B + row * (LDT * 2) + q * 16;
            CP_ASYNC16(dst, src + (size_t)gRow * P + k0 + q * 8);
        }
    };

    // ldmatrix lane addressing (byte offsets, row stride 80B) — validated R6-R15
    const int aRowOff = (lane & 7) + ((lane >> 3) & 1) * 8;
    const int aCbOff  = (lane >> 4) * 16;
    const int bRowOff = (lane & 7) + ((lane >> 4) & 1) * 8;
    const int bCbOff  = ((lane >> 3) & 1) * 16;

#pragma unroll
    for (int s = 0; s < NSTAGE - 1; s++) { issue(s); CP_COMMIT(); }

#pragma unroll 1
    for (int c = 0; c < NCH; c++) {
        if (c + NSTAGE - 1 < NCH) issue(c + NSTAGE - 1);
        CP_COMMIT();
        asm volatile("cp.async.wait_group %0;" :: "n"(NSTAGE - 1) : "memory");
        __syncthreads();

        const uint32_t sb = su + (uint32_t)(c % NSTAGE) * STAGE_B;
        const uint32_t aBase = sb, bBase = sb + TILE_B;

#pragma unroll
        for (int ks = 0; ks < 2; ks++) {
            uint32_t af[4][4], bf[2][4];
#pragma unroll
            for (int mi = 0; mi < 4; mi++)
                ldsm4(af[mi], aBase + (m64 + mi * 16 + aRowOff) * (LDT * 2) + ks * 32 + aCbOff);
#pragma unroll
            for (int np = 0; np < 2; np++)
                ldsm4(bf[np], bBase + (n32 + np * 16 + bRowOff) * (LDT * 2) + ks * 32 + bCbOff);
#pragma unroll
            for (int mi = 0; mi < 4; mi++)
#pragma unroll
                for (int np = 0; np < 2; np++) {
                    if (F16) {
                        mma_f16(acc[mi][np * 2 + 0], af[mi], bf[np][0], bf[np][1]);
                        mma_f16(acc[mi][np * 2 + 1], af[mi], bf[np][2], bf[np][3]);
                    } else {
                        mma_bf16(acc[mi][np * 2 + 0], af[mi], bf[np][0], bf[np][1]);
                        mma_bf16(acc[mi][np * 2 + 1], af[mi], bf[np][2], bf[np][3]);
                    }
                }
        }
        __syncthreads();
    }

    // ---------------- epilogue ----------------
    const int rq = lane >> 2;
    const int cq = (lane & 3) * 2;
    float locss = 0.f;
#pragma unroll
    for (int mi = 0; mi < 4; mi++) {
        int r0 = rowBase + m64 + mi * 16 + rq;
        int r1 = r0 + 8;
        float s0 = 0.f, s1 = 0.f;
        if (EPI == 0) { s0 = g_scale[r0]; s1 = g_scale[r1]; }
#pragma unroll
        for (int ni = 0; ni < 4; ni++) {
            int cg = colBase + n32 + ni * 8 + cq;
            float* d = acc[mi][ni];
            if (EPI == 0) {
                float v0 = s0 * d[0], v1 = s0 * d[1];
                float v2 = s1 * d[2], v3 = s1 * d[3];
                Cf32[(size_t)r0 * P + cg]     = v0;
                Cf32[(size_t)r0 * P + cg + 1] = v1;
                Cf32[(size_t)r1 * P + cg]     = v2;
                Cf32[(size_t)r1 * P + cg + 1] = v3;
                *(uint32_t*)(C16 + (size_t)r0 * P + cg) = pack_bf16(v0, v1);
                *(uint32_t*)(C16 + (size_t)r1 * P + cg) = pack_bf16(v2, v3);
            } else if (EPI == 1) {
                float2 f0 = __bfloat1622float2(*(const __nv_bfloat162*)(Dg16 + (size_t)r0 * P + cg));
                float2 f1 = __bfloat1622float2(*(const __nv_bfloat162*)(Dg16 + (size_t)r1 * P + cg));
                *(uint32_t*)(C16 + (size_t)r0 * P + cg) = pack_bf16(d[0] - f0.x, d[1] - f0.y);
                *(uint32_t*)(C16 + (size_t)r1 * P + cg) = pack_bf16(d[2] - f1.x, d[3] - f1.y);
            } else {
                locss += d[0] * d[0] + d[1] * d[1] + d[2] * d[2] + d[3] * d[3];
            }
        }
    }
    if (EPI == 2) {
        __syncthreads();
        float* red = (float*)smem;
        red[tid] = locss;
        __syncthreads();
        for (int s = NTH / 2; s > 0; s >>= 1) {
            if (tid < s) red[tid] += red[tid + s];
            __syncthreads();
        }
        if (tid == 0) atomicAdd(&g_ss, (double)red[0]);
    }
}

// ---------------------------------------------------------------- launch
extern "C" void kernel_launch(void* const* d_in, const int* in_sizes, int n_in,
                              void* d_out, int out_size) {
    const float* target = (const float*)d_in[0];
    const float* source = (const float*)d_in[1];
    const float* Wbeta  = (const float*)d_in[2];
    float* out = (float*)d_out;   // out[0]=loss, out[1:]=W_matrix

    __half *sF16, *tF16;
    __nv_bfloat16 *Wb16, *tgtT16, *srcT16, *Wm16, *PT16;
    cudaGetSymbolAddress((void**)&sF16, g_sF16);
    cudaGetSymbolAddress((void**)&tF16, g_tF16);
    cudaGetSymbolAddress((void**)&Wb16, g_Wb16);
    cudaGetSymbolAddress((void**)&tgtT16, g_tgtT16);
    cudaGetSymbolAddress((void**)&srcT16, g_srcT16);
    cudaGetSymbolAddress((void**)&Wm16, g_Wm16);
    cudaGetSymbolAddress((void**)&PT16, g_PT16);

    const int smemGemm = 4 * 2 * TILE_B;   // 81920 (4 stages x 2 tiles), 2 CTAs/SM
    cudaFuncSetAttribute((const void*)gemm_hmma<0, 4, true>,
                         cudaFuncAttributeMaxDynamicSharedMemorySize, smemGemm);
    cudaFuncSetAttribute((const void*)gemm_hmma<1, 4, false>,
                         cudaFuncAttributeMaxDynamicSharedMemorySize, smemGemm);
    cudaFuncSetAttribute((const void*)gemm_hmma<2, 4, false>,
                         cudaFuncAttributeMaxDynamicSharedMemorySize, smemGemm);

    zero_kernel<<<1, 1>>>();

    dim3 tgrid(P / 32, P / 32), tblk(32, 8);
    prep_target_kernel<<<tgrid, tblk>>>(target, tF16, tgtT16);   // tF16 + tgtT16 + sumsq
    prep_source_kernel<<<tgrid, tblk>>>(source, sF16, srcT16);   // sF16 + srcT16
    prep_wbeta_kernel<<<P / 8, tblk>>>(Wbeta, Wb16);             // Wb16 + row sums
    scale_kernel<<<P / NTH, NTH>>>();

    dim3 grid(P / BN, P / BM);  // 32 x 32
    // GEMM1 (fp16 single-pass): out[1+i*P+j] = scale[i]*sum_k src[i,k]*tgt[j,k]
    gemm_hmma<0, 4, true><<<grid, NTH, smemGemm>>>(
        (const uint16_t*)sF16, (const uint16_t*)tF16, nullptr, out + 1, Wm16);
    // GEMM2 (bf16; Wm ~4e-6 needs bf16 exponent range): PT16[j,i] = bf16(tgtT·Wm^T - srcT)
    gemm_hmma<1, 4, false><<<grid, NTH, smemGemm>>>(
        (const uint16_t*)tgtT16, (const uint16_t*)Wm16, srcT16, nullptr, PT16);
    // GEMM3 (bf16): g_ss += sum( (Wb @ PT^T)^2 )
    gemm_hmma<2, 4, false><<<grid, NTH, smemGemm>>>(
        (const uint16_t*)Wb16, (const uint16_t*)PT16, nullptr, nullptr, nullptr);

    final_kernel<<<1, 1>>>(out);
}

// round 17
// speedup vs baseline: 2.0092x; 1.1543x over previous
#include <cuda_runtime.h>
#include <cuda_bf16.h>
#include <cuda_fp16.h>
#include <cstdint>
#include <math.h>

#define P 4096
#define NTH 256
#define BM 128
#define BN 128
#define BKF 64                  // K elems per chunk (widened: fewer sync windows)
#define NCH (P / BKF)           // 64
#define LDT 72                  // padded smem row (16-bit elems) = 144B
#define TILE_B (128 * LDT * 2)  // 18432 B per operand tile

// ---------------------------------------------------------------- scratch
__device__ __half         g_sF16[(size_t)P * P];   // source (fp16)
__device__ __half         g_tF16[(size_t)P * P];   // target (fp16)
__device__ __nv_bfloat16  g_Wb16[(size_t)P * P];
__device__ __nv_bfloat16  g_tgtT16[(size_t)P * P];
__device__ __nv_bfloat16  g_srcT16[(size_t)P * P]; // source^T (bf16)
__device__ __nv_bfloat16  g_Wm16[(size_t)P * P];   // bf16: Wm ~4e-6 is fp16-subnormal!
__device__ __nv_bfloat16  g_PT16[(size_t)P * P];
__device__ float  g_W[P];
__device__ float  g_scale[P];
__device__ double g_s;
__device__ double g_ss;

// ---------------------------------------------------------------- helpers
__device__ __forceinline__ uint32_t smem_to_u32(const void* p) {
    uint32_t a;
    asm("{ .reg .u64 t; cvta.to.shared.u64 t, %1; cvt.u32.u64 %0, t; }" : "=r"(a) : "l"(p));
    return a;
}
__device__ __forceinline__ void ldsm4(uint32_t* r, uint32_t addr) {
    asm volatile("ldmatrix.sync.aligned.m8n8.x4.shared.b16 {%0,%1,%2,%3}, [%4];"
                 : "=r"(r[0]), "=r"(r[1]), "=r"(r[2]), "=r"(r[3]) : "r"(addr));
}
__device__ __forceinline__ void mma_bf16(float* d, const uint32_t* a, uint32_t b0, uint32_t b1) {
    asm volatile(
        "mma.sync.aligned.m16n8k16.row.col.f32.bf16.bf16.f32 "
        "{%0,%1,%2,%3}, {%4,%5,%6,%7}, {%8,%9}, {%0,%1,%2,%3};"
        : "+f"(d[0]), "+f"(d[1]), "+f"(d[2]), "+f"(d[3])
        : "r"(a[0]), "r"(a[1]), "r"(a[2]), "r"(a[3]), "r"(b0), "r"(b1));
}
__device__ __forceinline__ void mma_f16(float* d, const uint32_t* a, uint32_t b0, uint32_t b1) {
    asm volatile(
        "mma.sync.aligned.m16n8k16.row.col.f32.f16.f16.f32 "
        "{%0,%1,%2,%3}, {%4,%5,%6,%7}, {%8,%9}, {%0,%1,%2,%3};"
        : "+f"(d[0]), "+f"(d[1]), "+f"(d[2]), "+f"(d[3])
        : "r"(a[0]), "r"(a[1]), "r"(a[2]), "r"(a[3]), "r"(b0), "r"(b1));
}
#define CP_ASYNC16(dst, src) \
    asm volatile("cp.async.cg.shared.global [%0], [%1], 16;" :: "r"(dst), "l"(src) : "memory")
#define CP_COMMIT() asm volatile("cp.async.commit_group;" ::: "memory")

__device__ __forceinline__ uint32_t pack_bf16(float x, float y) {
    __nv_bfloat162 hb = __floats2bfloat162_rn(x, y);
    return *reinterpret_cast<uint32_t*>(&hb);
}

// ---------------------------------------------------------------- small kernels
__global__ void zero_kernel() { g_s = 0.0; g_ss = 0.0; }

// One read of target -> tF16 (straight fp16) + tgtT16 (transposed bf16) + sumsq
__global__ void prep_target_kernel(const float* __restrict__ in,
                                   __half* __restrict__ o16,
                                   __nv_bfloat16* __restrict__ oT) {
    __shared__ float tile[32][33];
    __shared__ float red[NTH];
    int x = blockIdx.x * 32 + threadIdx.x;
    int y0 = blockIdx.y * 32;
    float ss = 0.f;
    for (int j = threadIdx.y; j < 32; j += 8) {
        float v = in[(size_t)(y0 + j) * P + x];
        tile[j][threadIdx.x] = v;
        ss += v * v;
        o16[(size_t)(y0 + j) * P + x] = __float2half_rn(v);
    }
    int tid = threadIdx.y * 32 + threadIdx.x;
    red[tid] = ss;
    __syncthreads();
    for (int s = NTH / 2; s > 0; s >>= 1) {
        if (tid < s) red[tid] += red[tid + s];
        __syncthreads();
    }
    if (tid == 0) atomicAdd(&g_s, (double)red[0]);
    int x2 = blockIdx.y * 32 + threadIdx.x;
    int y2 = blockIdx.x * 32;
    for (int j = threadIdx.y; j < 32; j += 8)
        oT[(size_t)(y2 + j) * P + x2] = __float2bfloat16(tile[threadIdx.x][j]);
}

// One read of source -> sF16 (straight fp16) + srcT16 (transposed bf16)
__global__ void prep_source_kernel(const float* __restrict__ in,
                                   __half* __restrict__ o16,
                                   __nv_bfloat16* __restrict__ oT) {
    __shared__ float tile[32][33];
    int x = blockIdx.x * 32 + threadIdx.x;
    int y0 = blockIdx.y * 32;
    for (int j = threadIdx.y; j < 32; j += 8) {
        float v = in[(size_t)(y0 + j) * P + x];
        tile[j][threadIdx.x] = v;
        o16[(size_t)(y0 + j) * P + x] = __float2half_rn(v);
    }
    __syncthreads();
    int x2 = blockIdx.y * 32 + threadIdx.x;
    int y2 = blockIdx.x * 32;
    for (int j = threadIdx.y; j < 32; j += 8)
        oT[(size_t)(y2 + j) * P + x2] = __float2bfloat16(tile[threadIdx.x][j]);
}

// One read of Wbeta -> Wb16 + row sums (one warp per row, 8 rows per block)
__global__ void prep_wbeta_kernel(const float* __restrict__ Wb,
                                  __nv_bfloat16* __restrict__ o16) {
    int row = blockIdx.x * 8 + threadIdx.y;
    const float* rp = Wb + (size_t)row * P;
    float acc = 0.f;
#pragma unroll 4
    for (int it = 0; it < 32; it++) {
        int col = it * 128 + threadIdx.x * 4;
        float4 v = *(const float4*)(rp + col);
        acc += (v.x + v.y) + (v.z + v.w);
        *(uint2*)(o16 + (size_t)row * P + col) =
            make_uint2(pack_bf16(v.x, v.y), pack_bf16(v.z, v.w));
    }
#pragma unroll
    for (int o = 16; o > 0; o >>= 1) acc += __shfl_xor_sync(0xFFFFFFFFu, acc, o);
    if (threadIdx.x == 0) g_W[row] = acc;
}

__global__ void scale_kernel() {
    int i = blockIdx.x * blockDim.x + threadIdx.x;
    if (i < P) {
        float w = g_W[i], w2 = w * w;
        g_scale[i] = w2 / ((float)g_s * w2 + 1.0f);
    }
}

__global__ void final_kernel(float* __restrict__ out) { out[0] = (float)sqrt(g_ss); }

// ---------------------------------------------------------------- HMMA GEMM
// Geometry: CTA 128x128, 8 warps of 64x32, 2 CTAs/SM, NSTAGE=3, BKF=64.
// Row stride 144B: rows hit banks {0,4,..,28} (mod 32) per 8-row group ->
// conflict-free ldsm, same property as the validated 80B stride.
// EPI 0: Cf32 = scale[r]*acc (scalar stores into 4B-aligned out), C16 = bf16(same)
// EPI 1: C16 = bf16(acc - Dg16)   (Dg16 = bf16 source^T)
// EPI 2: g_ss += sum(acc^2)
template <int EPI, int NSTAGE, bool F16>
__global__ void __launch_bounds__(NTH, 2)
gemm_hmma(const uint16_t* __restrict__ A_, const uint16_t* __restrict__ B_,
          const __nv_bfloat16* __restrict__ Dg16, float* __restrict__ Cf32,
          __nv_bfloat16* __restrict__ C16) {
    extern __shared__ char smem[];
    const uint32_t su = smem_to_u32(smem);
    const int tid = threadIdx.x;
    const int lane = tid & 31;
    const int wid = tid >> 5;
    const int rowBase = blockIdx.y * BM;
    const int colBase = blockIdx.x * BN;
    const int m64 = (wid & 1) * 64;
    const int n32 = (wid >> 1) * 32;
    const uint32_t STAGE_B = 2 * TILE_B;

    float acc[4][4][4];
#pragma unroll
    for (int i = 0; i < 4; i++)
#pragma unroll
        for (int j = 0; j < 4; j++)
#pragma unroll
            for (int q = 0; q < 4; q++) acc[i][j][q] = 0.f;

    // cp.async producer: 1024 16B-transfers per tile (128 rows x 128B); tiles [A, B]
    auto issue = [&](int chunk) {
        const uint32_t sb = su + (uint32_t)(chunk % NSTAGE) * STAGE_B;
        const int k0 = chunk * BKF;
#pragma unroll
        for (int t = 0; t < 8; t++) {
            int idx = tid + t * NTH;
            int tile = idx >> 10;
            int within = idx & 1023;
            int row = within >> 3, q = within & 7;
            const uint16_t* src = (tile == 0) ? A_ : B_;
            int gRow = (tile == 0 ? rowBase : colBase) + row;
            uint32_t dst = sb + (uint32_t)tile * TILE_B + row * (LDT * 2) + q * 16;
            CP_ASYNC16(dst, src + (size_t)gRow * P + k0 + q * 8);
        }
    };

    // ldmatrix lane addressing (byte offsets, row stride 144B) — formulas from R6-R16
    const int aRowOff = (lane & 7) + ((lane >> 3) & 1) * 8;
    const int aCbOff  = (lane >> 4) * 16;
    const int bRowOff = (lane & 7) + ((lane >> 4) & 1) * 8;
    const int bCbOff  = ((lane >> 3) & 1) * 16;

#pragma unroll
    for (int s = 0; s < NSTAGE - 1; s++) { issue(s); CP_COMMIT(); }

#pragma unroll 1
    for (int c = 0; c < NCH; c++) {
        if (c + NSTAGE - 1 < NCH) issue(c + NSTAGE - 1);
        CP_COMMIT();
        asm volatile("cp.async.wait_group %0;" :: "n"(NSTAGE - 1) : "memory");
        __syncthreads();

        const uint32_t sb = su + (uint32_t)(c % NSTAGE) * STAGE_B;
        const uint32_t aBase = sb, bBase = sb + TILE_B;

#pragma unroll
        for (int ks = 0; ks < 4; ks++) {   // 4 K=16 windows per 64-elem chunk
            uint32_t af[4][4], bf[2][4];
#pragma unroll
            for (int mi = 0; mi < 4; mi++)
                ldsm4(af[mi], aBase + (m64 + mi * 16 + aRowOff) * (LDT * 2) + ks * 32 + aCbOff);
#pragma unroll
            for (int np = 0; np < 2; np++)
                ldsm4(bf[np], bBase + (n32 + np * 16 + bRowOff) * (LDT * 2) + ks * 32 + bCbOff);
#pragma unroll
            for (int mi = 0; mi < 4; mi++)
#pragma unroll
                for (int np = 0; np < 2; np++) {
                    if (F16) {
                        mma_f16(acc[mi][np * 2 + 0], af[mi], bf[np][0], bf[np][1]);
                        mma_f16(acc[mi][np * 2 + 1], af[mi], bf[np][2], bf[np][3]);
                    } else {
                        mma_bf16(acc[mi][np * 2 + 0], af[mi], bf[np][0], bf[np][1]);
                        mma_bf16(acc[mi][np * 2 + 1], af[mi], bf[np][2], bf[np][3]);
                    }
                }
        }
        __syncthreads();
    }

    // ---------------- epilogue ----------------
    const int rq = lane >> 2;
    const int cq = (lane & 3) * 2;
    float locss = 0.f;
#pragma unroll
    for (int mi = 0; mi < 4; mi++) {
        int r0 = rowBase + m64 + mi * 16 + rq;
        int r1 = r0 + 8;
        float s0 = 0.f, s1 = 0.f;
        if (EPI == 0) { s0 = g_scale[r0]; s1 = g_scale[r1]; }
#pragma unroll
        for (int ni = 0; ni < 4; ni++) {
            int cg = colBase + n32 + ni * 8 + cq;
            float* d = acc[mi][ni];
            if (EPI == 0) {
                float v0 = s0 * d[0], v1 = s0 * d[1];
                float v2 = s1 * d[2], v3 = s1 * d[3];
                Cf32[(size_t)r0 * P + cg]     = v0;
                Cf32[(size_t)r0 * P + cg + 1] = v1;
                Cf32[(size_t)r1 * P + cg]     = v2;
                Cf32[(size_t)r1 * P + cg + 1] = v3;
                *(uint32_t*)(C16 + (size_t)r0 * P + cg) = pack_bf16(v0, v1);
                *(uint32_t*)(C16 + (size_t)r1 * P + cg) = pack_bf16(v2, v3);
            } else if (EPI == 1) {
                float2 f0 = __bfloat1622float2(*(const __nv_bfloat162*)(Dg16 + (size_t)r0 * P + cg));
                float2 f1 = __bfloat1622float2(*(const __nv_bfloat162*)(Dg16 + (size_t)r1 * P + cg));
                *(uint32_t*)(C16 + (size_t)r0 * P + cg) = pack_bf16(d[0] - f0.x, d[1] - f0.y);
                *(uint32_t*)(C16 + (size_t)r1 * P + cg) = pack_bf16(d[2] - f1.x, d[3] - f1.y);
            } else {
                locss += d[0] * d[0] + d[1] * d[1] + d[2] * d[2] + d[3] * d[3];
            }
        }
    }
    if (EPI == 2) {
        __syncthreads();
        float* red = (float*)smem;
        red[tid] = locss;
        __syncthreads();
        for (int s = NTH / 2; s > 0; s >>= 1) {
            if (tid < s) red[tid] += red[tid + s];
            __syncthreads();
        }
        if (tid == 0) atomicAdd(&g_ss, (double)red[0]);
    }
}

// ---------------------------------------------------------------- launch
extern "C" void kernel_launch(void* const* d_in, const int* in_sizes, int n_in,
                              void* d_out, int out_size) {
    const float* target = (const float*)d_in[0];
    const float* source = (const float*)d_in[1];
    const float* Wbeta  = (const float*)d_in[2];
    float* out = (float*)d_out;   // out[0]=loss, out[1:]=W_matrix

    __half *sF16, *tF16;
    __nv_bfloat16 *Wb16, *tgtT16, *srcT16, *Wm16, *PT16;
    cudaGetSymbolAddress((void**)&sF16, g_sF16);
    cudaGetSymbolAddress((void**)&tF16, g_tF16);
    cudaGetSymbolAddress((void**)&Wb16, g_Wb16);
    cudaGetSymbolAddress((void**)&tgtT16, g_tgtT16);
    cudaGetSymbolAddress((void**)&srcT16, g_srcT16);
    cudaGetSymbolAddress((void**)&Wm16, g_Wm16);
    cudaGetSymbolAddress((void**)&PT16, g_PT16);

    const int smemGemm = 3 * 2 * TILE_B;   // 110592 (3 stages x 2 tiles), 2 CTAs/SM
    cudaFuncSetAttribute((const void*)gemm_hmma<0, 3, true>,
                         cudaFuncAttributeMaxDynamicSharedMemorySize, smemGemm);
    cudaFuncSetAttribute((const void*)gemm_hmma<1, 3, false>,
                         cudaFuncAttributeMaxDynamicSharedMemorySize, smemGemm);
    cudaFuncSetAttribute((const void*)gemm_hmma<2, 3, false>,
                         cudaFuncAttributeMaxDynamicSharedMemorySize, smemGemm);

    zero_kernel<<<1, 1>>>();

    dim3 tgrid(P / 32, P / 32), tblk(32, 8);
    prep_target_kernel<<<tgrid, tblk>>>(target, tF16, tgtT16);   // tF16 + tgtT16 + sumsq
    prep_source_kernel<<<tgrid, tblk>>>(source, sF16, srcT16);   // sF16 + srcT16
    prep_wbeta_kernel<<<P / 8, tblk>>>(Wbeta, Wb16);             // Wb16 + row sums
    scale_kernel<<<P / NTH, NTH>>>();

    dim3 grid(P / BN, P / BM);  // 32 x 32
    // GEMM1 (fp16 single-pass): out[1+i*P+j] = scale[i]*sum_k src[i,k]*tgt[j,k]
    gemm_hmma<0, 3, true><<<grid, NTH, smemGemm>>>(
        (const uint16_t*)sF16, (const uint16_t*)tF16, nullptr, out + 1, Wm16);
    // GEMM2 (bf16; Wm ~4e-6 needs bf16 exponent range): PT16[j,i] = bf16(tgtT·Wm^T - srcT)
    gemm_hmma<1, 3, false><<<grid, NTH, smemGemm>>>(
        (const uint16_t*)tgtT16, (const uint16_t*)Wm16, srcT16, nullptr, PT16);
    // GEMM3 (bf16): g_ss += sum( (Wb @ PT^T)^2 )
    gemm_hmma<2, 3, false><<<grid, NTH, smemGemm>>>(
        (const uint16_t*)Wb16, (const uint16_t*)PT16, nullptr, nullptr, nullptr);

    final_kernel<<<1, 1>>>(out);
}